// round 1
// baseline (speedup 1.0000x reference)
#include <cuda_runtime.h>
#include <mma.h>
#include <math.h>

using namespace nvcuda;

#define HDIM 2880
#define NEXP 16
#define I2   5760      // 2*I
#define IDIM 2880
#define NTOK 1024
#define TOPK 4
#define ALPHA_C 1.702f
#define LIMIT_C 7.0f

#define BM 64
#define BN 64
#define BK 16
#define LDS_AB 20      // BK + 4 pad
#define LDS_C  68      // BN + 4 pad

// -------- device scratch (static; no allocations) --------
__device__ int   g_cnt[NEXP];
__device__ int   g_tok[NEXP * NTOK];
__device__ float g_prob[NEXP * NTOK];
__device__ float g_act[NEXP * NTOK * IDIM];   // 189 MB fp32 activation scratch

// =========================================================
// zero output + counters
// =========================================================
__global__ void zero_kernel(float* __restrict__ out) {
    int i = blockIdx.x * blockDim.x + threadIdx.x;
    if (i < NTOK * HDIM) out[i] = 0.0f;
    if (i < NEXP) g_cnt[i] = 0;
}

// =========================================================
// router: logits -> top4 -> softmax -> per-expert lists
// one block (128 thr) per token
// =========================================================
__global__ void router_kernel(const float* __restrict__ x,
                              const float* __restrict__ rw,
                              const float* __restrict__ rb) {
    int t = blockIdx.x;
    const float* xr = x + t * HDIM;

    float acc[NEXP];
#pragma unroll
    for (int e = 0; e < NEXP; e++) acc[e] = 0.0f;

    for (int h = threadIdx.x; h < HDIM; h += 128) {
        float xv = xr[h];
#pragma unroll
        for (int e = 0; e < NEXP; e++) acc[e] += xv * rw[e * HDIM + h];
    }
    // warp reduce
#pragma unroll
    for (int e = 0; e < NEXP; e++) {
#pragma unroll
        for (int o = 16; o > 0; o >>= 1)
            acc[e] += __shfl_down_sync(0xffffffffu, acc[e], o);
    }
    __shared__ float red[4][NEXP];
    int warp = threadIdx.x >> 5, lane = threadIdx.x & 31;
    if (lane == 0) {
#pragma unroll
        for (int e = 0; e < NEXP; e++) red[warp][e] = acc[e];
    }
    __syncthreads();
    if (threadIdx.x == 0) {
        float lg[NEXP];
#pragma unroll
        for (int e = 0; e < NEXP; e++)
            lg[e] = red[0][e] + red[1][e] + red[2][e] + red[3][e] + rb[e];

        int   idx[TOPK];
        float val[TOPK];
        bool  used[NEXP];
#pragma unroll
        for (int e = 0; e < NEXP; e++) used[e] = false;
        for (int k = 0; k < TOPK; k++) {
            int bi = -1; float bv = -3.0e38f;
            for (int e = 0; e < NEXP; e++)
                if (!used[e] && lg[e] > bv) { bv = lg[e]; bi = e; }
            used[bi] = true; idx[k] = bi; val[k] = bv;
        }
        float m = val[0];
        float s = 0.0f, p[TOPK];
        for (int k = 0; k < TOPK; k++) { p[k] = expf(val[k] - m); s += p[k]; }
        for (int k = 0; k < TOPK; k++) {
            int e = idx[k];
            int pos = atomicAdd(&g_cnt[e], 1);
            g_tok[e * NTOK + pos]  = t;
            g_prob[e * NTOK + pos] = p[k] / s;
        }
    }
}

// =========================================================
// FFN1: per expert  act = glu( gather(X) @ w1e^T + b1e )
// grid: (m_tiles=16, n_tiles=90, experts=16), 128 threads
// =========================================================
__global__ void __launch_bounds__(128)
ffn1_kernel(const float* __restrict__ X,
            const float* __restrict__ w1,
            const float* __restrict__ b1) {
    int e   = blockIdx.z;
    int cnt = g_cnt[e];
    int m0  = blockIdx.x * BM;
    if (m0 >= cnt) return;
    int n0  = blockIdx.y * BN;

    __shared__ float sA[BM * LDS_AB];
    __shared__ float sB[BN * LDS_AB];
    __shared__ float sC[BM * LDS_C];

    int tid  = threadIdx.x;
    int warp = tid >> 5;
    int wm = warp >> 1, wn = warp & 1;

    const float* aptr[2];
    const float* bptr[2];
    const float* bbase = w1 + (size_t)e * I2 * HDIM;
#pragma unroll
    for (int i = 0; i < 2; i++) {
        int idx  = tid + i * 128;
        int row  = idx >> 2;
        int quad = idx & 3;
        int rg   = m0 + row;
        int tok  = g_tok[e * NTOK + (rg < cnt ? rg : cnt - 1)];
        aptr[i] = X + (size_t)tok * HDIM + quad * 4;
        bptr[i] = bbase + (size_t)(n0 + row) * HDIM + quad * 4;
    }

    wmma::fragment<wmma::accumulator, 16, 16, 8, float> c[2][2];
#pragma unroll
    for (int a = 0; a < 2; a++)
#pragma unroll
        for (int b = 0; b < 2; b++) wmma::fill_fragment(c[a][b], 0.0f);

    for (int k0 = 0; k0 < HDIM; k0 += BK) {
#pragma unroll
        for (int i = 0; i < 2; i++) {
            int idx  = tid + i * 128;
            int row  = idx >> 2;
            int quad = idx & 3;
            float4 va = *reinterpret_cast<const float4*>(aptr[i] + k0);
            *reinterpret_cast<float4*>(&sA[row * LDS_AB + quad * 4]) = va;
            float4 vb = *reinterpret_cast<const float4*>(bptr[i] + k0);
            *reinterpret_cast<float4*>(&sB[row * LDS_AB + quad * 4]) = vb;
        }
        __syncthreads();
#pragma unroll
        for (int kk = 0; kk < BK; kk += 8) {
            wmma::fragment<wmma::matrix_a, 16, 16, 8, wmma::precision::tf32, wmma::row_major> af[2];
            wmma::fragment<wmma::matrix_b, 16, 16, 8, wmma::precision::tf32, wmma::col_major> bf[2];
#pragma unroll
            for (int i = 0; i < 2; i++) {
                wmma::load_matrix_sync(af[i], &sA[(wm * 32 + i * 16) * LDS_AB + kk], LDS_AB);
#pragma unroll
                for (int x = 0; x < af[i].num_elements; x++)
                    af[i].x[x] = wmma::__float_to_tf32(af[i].x[x]);
                wmma::load_matrix_sync(bf[i], &sB[(wn * 32 + i * 16) * LDS_AB + kk], LDS_AB);
#pragma unroll
                for (int x = 0; x < bf[i].num_elements; x++)
                    bf[i].x[x] = wmma::__float_to_tf32(bf[i].x[x]);
            }
#pragma unroll
            for (int a = 0; a < 2; a++)
#pragma unroll
                for (int b = 0; b < 2; b++)
                    wmma::mma_sync(c[a][b], af[a], bf[b], c[a][b]);
        }
        __syncthreads();
    }

#pragma unroll
    for (int a = 0; a < 2; a++)
#pragma unroll
        for (int b = 0; b < 2; b++)
            wmma::store_matrix_sync(&sC[(wm * 32 + a * 16) * LDS_C + wn * 32 + b * 16],
                                    c[a][b], LDS_C, wmma::mem_row_major);
    __syncthreads();

    const float* b1e = b1 + e * I2;
    for (int idx = tid; idx < BM * (BN / 2); idx += 128) {
        int row = idx >> 5;          // BN/2 = 32 pairs per row
        int pr  = idx & 31;
        int rg  = m0 + row;
        if (rg >= cnt) continue;
        float gate = sC[row * LDS_C + 2 * pr]     + b1e[n0 + 2 * pr];
        float up   = sC[row * LDS_C + 2 * pr + 1] + b1e[n0 + 2 * pr + 1];
        gate = fminf(gate, LIMIT_C);
        up   = fminf(fmaxf(up, -LIMIT_C), LIMIT_C);
        float act = (up + 1.0f) * (gate / (1.0f + expf(-ALPHA_C * gate)));
        g_act[(e * NTOK + rg) * IDIM + (n0 >> 1) + pr] = act;
    }
}

// =========================================================
// FFN2: out += prob * ( act @ w2e^T + b2e )  (atomic scatter)
// grid: (m_tiles=16, n_tiles=45, experts=16), 128 threads
// =========================================================
__global__ void __launch_bounds__(128)
ffn2_kernel(const float* __restrict__ w2,
            const float* __restrict__ b2,
            float* __restrict__ out) {
    int e   = blockIdx.z;
    int cnt = g_cnt[e];
    int m0  = blockIdx.x * BM;
    if (m0 >= cnt) return;
    int n0  = blockIdx.y * BN;

    __shared__ float sA[BM * LDS_AB];
    __shared__ float sB[BN * LDS_AB];
    __shared__ float sC[BM * LDS_C];

    int tid  = threadIdx.x;
    int warp = tid >> 5;
    int wm = warp >> 1, wn = warp & 1;

    const float* aptr[2];
    const float* bptr[2];
    const float* bbase = w2 + (size_t)e * HDIM * IDIM;
#pragma unroll
    for (int i = 0; i < 2; i++) {
        int idx  = tid + i * 128;
        int row  = idx >> 2;
        int quad = idx & 3;
        int rg   = m0 + row;
        int rc   = (rg < cnt ? rg : cnt - 1);
        aptr[i] = g_act + (size_t)(e * NTOK + rc) * IDIM + quad * 4;
        bptr[i] = bbase + (size_t)(n0 + row) * IDIM + quad * 4;
    }

    wmma::fragment<wmma::accumulator, 16, 16, 8, float> c[2][2];
#pragma unroll
    for (int a = 0; a < 2; a++)
#pragma unroll
        for (int b = 0; b < 2; b++) wmma::fill_fragment(c[a][b], 0.0f);

    for (int k0 = 0; k0 < IDIM; k0 += BK) {
#pragma unroll
        for (int i = 0; i < 2; i++) {
            int idx  = tid + i * 128;
            int row  = idx >> 2;
            int quad = idx & 3;
            float4 va = *reinterpret_cast<const float4*>(aptr[i] + k0);
            *reinterpret_cast<float4*>(&sA[row * LDS_AB + quad * 4]) = va;
            float4 vb = *reinterpret_cast<const float4*>(bptr[i] + k0);
            *reinterpret_cast<float4*>(&sB[row * LDS_AB + quad * 4]) = vb;
        }
        __syncthreads();
#pragma unroll
        for (int kk = 0; kk < BK; kk += 8) {
            wmma::fragment<wmma::matrix_a, 16, 16, 8, wmma::precision::tf32, wmma::row_major> af[2];
            wmma::fragment<wmma::matrix_b, 16, 16, 8, wmma::precision::tf32, wmma::col_major> bf[2];
#pragma unroll
            for (int i = 0; i < 2; i++) {
                wmma::load_matrix_sync(af[i], &sA[(wm * 32 + i * 16) * LDS_AB + kk], LDS_AB);
#pragma unroll
                for (int x = 0; x < af[i].num_elements; x++)
                    af[i].x[x] = wmma::__float_to_tf32(af[i].x[x]);
                wmma::load_matrix_sync(bf[i], &sB[(wn * 32 + i * 16) * LDS_AB + kk], LDS_AB);
#pragma unroll
                for (int x = 0; x < bf[i].num_elements; x++)
                    bf[i].x[x] = wmma::__float_to_tf32(bf[i].x[x]);
            }
#pragma unroll
            for (int a = 0; a < 2; a++)
#pragma unroll
                for (int b = 0; b < 2; b++)
                    wmma::mma_sync(c[a][b], af[a], bf[b], c[a][b]);
        }
        __syncthreads();
    }

#pragma unroll
    for (int a = 0; a < 2; a++)
#pragma unroll
        for (int b = 0; b < 2; b++)
            wmma::store_matrix_sync(&sC[(wm * 32 + a * 16) * LDS_C + wn * 32 + b * 16],
                                    c[a][b], LDS_C, wmma::mem_row_major);
    __syncthreads();

    for (int idx = tid; idx < BM * BN; idx += 128) {
        int row = idx >> 6;
        int col = idx & 63;
        int rg  = m0 + row;
        if (rg >= cnt) continue;
        float v = (sC[row * LDS_C + col] + b2[e * HDIM + n0 + col]) * g_prob[e * NTOK + rg];
        atomicAdd(&out[(size_t)g_tok[e * NTOK + rg] * HDIM + n0 + col], v);
    }
}

// =========================================================
extern "C" void kernel_launch(void* const* d_in, const int* in_sizes, int n_in,
                              void* d_out, int out_size) {
    const float* hidden = (const float*)d_in[0];
    const float* rw     = (const float*)d_in[1];
    const float* rb     = (const float*)d_in[2];
    const float* w1     = (const float*)d_in[3];
    const float* b1     = (const float*)d_in[4];
    const float* w2     = (const float*)d_in[5];
    const float* b2     = (const float*)d_in[6];
    float* out = (float*)d_out;

    zero_kernel<<<(NTOK * HDIM + 255) / 256, 256>>>(out);
    router_kernel<<<NTOK, 128>>>(hidden, rw, rb);
    ffn1_kernel<<<dim3(NTOK / BM, I2 / BN, NEXP), 128>>>(hidden, w1, b1);
    ffn2_kernel<<<dim3(NTOK / BM, HDIM / BN, NEXP), 128>>>(w2, b2, out);
}

// round 3
// speedup vs baseline: 1.0944x; 1.0944x over previous
#include <cuda_runtime.h>
#include <cstdint>
#include <mma.h>
#include <math.h>

using namespace nvcuda;

#define HDIM 2880
#define NEXP 16
#define I2   5760      // 2*I
#define IDIM 2880
#define NTOK 1024
#define TOPK 4
#define ALPHA_C 1.702f
#define LIMIT_C 7.0f

#define BM 128
#define BN 128
#define BK 16
#define LDS_AB 20            // BK + 4 pad (floats)
#define LDS_C  132           // BN + 4 pad (floats)
#define STG_F  (BM * LDS_AB) // floats per stage per matrix = 2560
#define SMEM_BYTES (BM * LDS_C * 4)   // 67584 B (union: stages use 40960 B)

// -------- device scratch (static; no allocations) --------
__device__ int   g_cnt[NEXP];
__device__ int   g_tok[NEXP * NTOK];
__device__ float g_prob[NEXP * NTOK];
__device__ float g_act[NEXP * NTOK * IDIM];

// ---------------- cp.async helpers ----------------
__device__ __forceinline__ void cp_async16(float* smem_ptr, const float* gptr) {
    unsigned int s = (unsigned int)__cvta_generic_to_shared(smem_ptr);
    asm volatile("cp.async.cg.shared.global [%0], [%1], 16;\n" :: "r"(s), "l"(gptr));
}
__device__ __forceinline__ void cp_commit() {
    asm volatile("cp.async.commit_group;\n");
}
template<int N>
__device__ __forceinline__ void cp_wait() {
    asm volatile("cp.async.wait_group %0;\n" :: "n"(N));
}

// =========================================================
// zero output + counters
// =========================================================
__global__ void zero_kernel(float* __restrict__ out) {
    int i = blockIdx.x * blockDim.x + threadIdx.x;
    if (i < NTOK * HDIM) out[i] = 0.0f;
    if (i < NEXP) g_cnt[i] = 0;
}

// =========================================================
// router: logits -> top4 -> softmax -> per-expert lists
// =========================================================
__global__ void router_kernel(const float* __restrict__ x,
                              const float* __restrict__ rw,
                              const float* __restrict__ rb) {
    int t = blockIdx.x;
    const float* xr = x + t * HDIM;

    float acc[NEXP];
#pragma unroll
    for (int e = 0; e < NEXP; e++) acc[e] = 0.0f;

    for (int h = threadIdx.x; h < HDIM; h += 128) {
        float xv = xr[h];
#pragma unroll
        for (int e = 0; e < NEXP; e++) acc[e] += xv * rw[e * HDIM + h];
    }
#pragma unroll
    for (int e = 0; e < NEXP; e++) {
#pragma unroll
        for (int o = 16; o > 0; o >>= 1)
            acc[e] += __shfl_down_sync(0xffffffffu, acc[e], o);
    }
    __shared__ float red[4][NEXP];
    int warp = threadIdx.x >> 5, lane = threadIdx.x & 31;
    if (lane == 0) {
#pragma unroll
        for (int e = 0; e < NEXP; e++) red[warp][e] = acc[e];
    }
    __syncthreads();
    if (threadIdx.x == 0) {
        float lg[NEXP];
#pragma unroll
        for (int e = 0; e < NEXP; e++)
            lg[e] = red[0][e] + red[1][e] + red[2][e] + red[3][e] + rb[e];

        int   idx[TOPK];
        float val[TOPK];
        bool  used[NEXP];
#pragma unroll
        for (int e = 0; e < NEXP; e++) used[e] = false;
        for (int k = 0; k < TOPK; k++) {
            int bi = -1; float bv = -3.0e38f;
            for (int e = 0; e < NEXP; e++)
                if (!used[e] && lg[e] > bv) { bv = lg[e]; bi = e; }
            used[bi] = true; idx[k] = bi; val[k] = bv;
        }
        float m = val[0];
        float s = 0.0f, p[TOPK];
        for (int k = 0; k < TOPK; k++) { p[k] = expf(val[k] - m); s += p[k]; }
        for (int k = 0; k < TOPK; k++) {
            int e = idx[k];
            int pos = atomicAdd(&g_cnt[e], 1);
            g_tok[e * NTOK + pos]  = t;
            g_prob[e * NTOK + pos] = p[k] / s;
        }
    }
}

// =========================================================
// Shared GEMM mainloop.
// Computes 128x128 tf32 GEMM tile: C = A(gathered rows) * B^T
// =========================================================
struct Frag {
    wmma::fragment<wmma::accumulator, 16, 16, 8, float> c[2][4];
};

__device__ __forceinline__ void gemm_mainloop(
    float* dsm, const float* aptr0, const float* aptr1,
    const float* bptr0, const float* bptr1, int kdim,
    int tid, Frag& fr)
{
    float* sA[2] = { dsm,             dsm + STG_F };
    float* sB[2] = { dsm + 2 * STG_F, dsm + 3 * STG_F };

    int warp = tid >> 5;
    int wm = warp >> 1;          // 0..3  (32-row group)
    int wn = warp & 1;           // 0..1  (64-col group)

    int row0 = tid >> 2, quad0 = tid & 3;
    int idx1 = tid + 256;
    int row1 = idx1 >> 2, quad1 = idx1 & 3;

    const int KT = kdim / BK;

    // prologue: stage 0
    cp_async16(&sA[0][row0 * LDS_AB + quad0 * 4], aptr0);
    cp_async16(&sA[0][row1 * LDS_AB + quad1 * 4], aptr1);
    cp_async16(&sB[0][row0 * LDS_AB + quad0 * 4], bptr0);
    cp_async16(&sB[0][row1 * LDS_AB + quad1 * 4], bptr1);
    cp_commit();

#pragma unroll
    for (int a = 0; a < 2; a++)
#pragma unroll
        for (int b = 0; b < 4; b++) wmma::fill_fragment(fr.c[a][b], 0.0f);

    for (int kt = 0; kt < KT; kt++) {
        int s = kt & 1;
        if (kt + 1 < KT) {
            int ns = s ^ 1;
            int k0 = (kt + 1) * BK;
            cp_async16(&sA[ns][row0 * LDS_AB + quad0 * 4], aptr0 + k0);
            cp_async16(&sA[ns][row1 * LDS_AB + quad1 * 4], aptr1 + k0);
            cp_async16(&sB[ns][row0 * LDS_AB + quad0 * 4], bptr0 + k0);
            cp_async16(&sB[ns][row1 * LDS_AB + quad1 * 4], bptr1 + k0);
            cp_commit();
            cp_wait<1>();
        } else {
            cp_wait<0>();
        }
        __syncthreads();

#pragma unroll
        for (int kk = 0; kk < BK; kk += 8) {
            wmma::fragment<wmma::matrix_a, 16, 16, 8, wmma::precision::tf32, wmma::row_major> af[2];
            wmma::fragment<wmma::matrix_b, 16, 16, 8, wmma::precision::tf32, wmma::col_major> bf[4];
#pragma unroll
            for (int i = 0; i < 2; i++) {
                wmma::load_matrix_sync(af[i], &sA[s][(wm * 32 + i * 16) * LDS_AB + kk], LDS_AB);
#pragma unroll
                for (int x = 0; x < af[i].num_elements; x++)
                    af[i].x[x] = wmma::__float_to_tf32(af[i].x[x]);
            }
#pragma unroll
            for (int j = 0; j < 4; j++) {
                wmma::load_matrix_sync(bf[j], &sB[s][(wn * 64 + j * 16) * LDS_AB + kk], LDS_AB);
#pragma unroll
                for (int x = 0; x < bf[j].num_elements; x++)
                    bf[j].x[x] = wmma::__float_to_tf32(bf[j].x[x]);
            }
#pragma unroll
            for (int i = 0; i < 2; i++)
#pragma unroll
                for (int j = 0; j < 4; j++)
                    wmma::mma_sync(fr.c[i][j], af[i], bf[j], fr.c[i][j]);
        }
        __syncthreads();
    }
}

__device__ __forceinline__ void store_frags(float* dsm, int tid, Frag& fr) {
    int warp = tid >> 5;
    int wm = warp >> 1, wn = warp & 1;
#pragma unroll
    for (int i = 0; i < 2; i++)
#pragma unroll
        for (int j = 0; j < 4; j++)
            wmma::store_matrix_sync(&dsm[(wm * 32 + i * 16) * LDS_C + wn * 64 + j * 16],
                                    fr.c[i][j], LDS_C, wmma::mem_row_major);
}

// =========================================================
// FFN1: act = glu( gather(X) @ w1e^T + b1e )
// grid: (8, 45, 16), 256 threads
// =========================================================
__global__ void __launch_bounds__(256)
ffn1_kernel(const float* __restrict__ X,
            const float* __restrict__ w1,
            const float* __restrict__ b1) {
    int e   = blockIdx.z;
    int cnt = g_cnt[e];
    int m0  = blockIdx.x * BM;
    if (m0 >= cnt) return;
    int n0  = blockIdx.y * BN;

    extern __shared__ float dsm[];
    int tid = threadIdx.x;

    const float* bbase = w1 + (size_t)e * I2 * HDIM;
    const float* ap[2];
    const float* bp[2];
#pragma unroll
    for (int i = 0; i < 2; i++) {
        int idx  = tid + i * 256;
        int row  = idx >> 2;
        int quad = idx & 3;
        int rg   = m0 + row;
        int tok  = g_tok[e * NTOK + (rg < cnt ? rg : cnt - 1)];
        ap[i] = X + (size_t)tok * HDIM + quad * 4;
        bp[i] = bbase + (size_t)(n0 + row) * HDIM + quad * 4;
    }

    Frag fr;
    gemm_mainloop(dsm, ap[0], ap[1], bp[0], bp[1], HDIM, tid, fr);

    __syncthreads();          // stages dead; reuse dsm as sC
    store_frags(dsm, tid, fr);
    __syncthreads();

    const float* b1e = b1 + e * I2;
    for (int idx = tid; idx < BM * (BN / 2); idx += 256) {
        int row = idx >> 6;          // 64 pairs per row
        int pr  = idx & 63;
        int rg  = m0 + row;
        if (rg >= cnt) continue;
        float gate = dsm[row * LDS_C + 2 * pr]     + b1e[n0 + 2 * pr];
        float up   = dsm[row * LDS_C + 2 * pr + 1] + b1e[n0 + 2 * pr + 1];
        gate = fminf(gate, LIMIT_C);
        up   = fminf(fmaxf(up, -LIMIT_C), LIMIT_C);
        float act = (up + 1.0f) * (gate / (1.0f + expf(-ALPHA_C * gate)));
        g_act[(size_t)(e * NTOK + rg) * IDIM + (n0 >> 1) + pr] = act;
    }
}

// =========================================================
// FFN2: out += prob * ( act @ w2e^T + b2e )
// grid: (8, 23, 16), 256 threads
// =========================================================
__global__ void __launch_bounds__(256)
ffn2_kernel(const float* __restrict__ w2,
            const float* __restrict__ b2,
            float* __restrict__ out) {
    int e   = blockIdx.z;
    int cnt = g_cnt[e];
    int m0  = blockIdx.x * BM;
    if (m0 >= cnt) return;
    int n0  = blockIdx.y * BN;

    extern __shared__ float dsm[];
    int tid = threadIdx.x;

    const float* bbase = w2 + (size_t)e * HDIM * IDIM;
    const float* ap[2];
    const float* bp[2];
#pragma unroll
    for (int i = 0; i < 2; i++) {
        int idx  = tid + i * 256;
        int row  = idx >> 2;
        int quad = idx & 3;
        int rg   = m0 + row;
        int rc   = (rg < cnt ? rg : cnt - 1);
        ap[i] = g_act + (size_t)(e * NTOK + rc) * IDIM + quad * 4;
        int rb = n0 + row; if (rb >= HDIM) rb = HDIM - 1;
        bp[i] = bbase + (size_t)rb * IDIM + quad * 4;
    }

    Frag fr;
    gemm_mainloop(dsm, ap[0], ap[1], bp[0], bp[1], IDIM, tid, fr);

    __syncthreads();
    store_frags(dsm, tid, fr);
    __syncthreads();

    for (int idx = tid; idx < BM * BN; idx += 256) {
        int row = idx >> 7;
        int col = idx & 127;
        int rg  = m0 + row;
        int nc  = n0 + col;
        if (rg >= cnt || nc >= HDIM) continue;
        float v = (dsm[row * LDS_C + col] + b2[e * HDIM + nc]) * g_prob[e * NTOK + rg];
        atomicAdd(&out[(size_t)g_tok[e * NTOK + rg] * HDIM + nc], v);
    }
}

// =========================================================
extern "C" void kernel_launch(void* const* d_in, const int* in_sizes, int n_in,
                              void* d_out, int out_size) {
    const float* hidden = (const float*)d_in[0];
    const float* rw     = (const float*)d_in[1];
    const float* rb     = (const float*)d_in[2];
    const float* w1     = (const float*)d_in[3];
    const float* b1     = (const float*)d_in[4];
    const float* w2     = (const float*)d_in[5];
    const float* b2     = (const float*)d_in[6];
    float* out = (float*)d_out;

    cudaFuncSetAttribute(ffn1_kernel, cudaFuncAttributeMaxDynamicSharedMemorySize, SMEM_BYTES);
    cudaFuncSetAttribute(ffn2_kernel, cudaFuncAttributeMaxDynamicSharedMemorySize, SMEM_BYTES);

    zero_kernel<<<(NTOK * HDIM + 255) / 256, 256>>>(out);
    router_kernel<<<NTOK, 128>>>(hidden, rw, rb);
    ffn1_kernel<<<dim3(NTOK / BM, I2 / BN, NEXP), 256, SMEM_BYTES>>>(hidden, w1, b1);
    ffn2_kernel<<<dim3(NTOK / BM, (HDIM + BN - 1) / BN, NEXP), 256, SMEM_BYTES>>>(w2, b2, out);
}

// round 5
// speedup vs baseline: 2.5070x; 2.2907x over previous
#include <cuda_runtime.h>
#include <cuda_fp16.h>
#include <cstdint>
#include <mma.h>
#include <math.h>

using namespace nvcuda;

#define HDIM 2880
#define NEXP 16
#define I2   5760
#define IDIM 2880
#define NTOK 1024
#define TOPK 4
#define ALPHA_C 1.702f
#define LIMIT_C 7.0f

#define BM 128
#define BN 128
#define BK 32
#define LDSH 40                  // halves per smem row (32 + 8 pad) = 80B
#define STAGE_BYTES 20480        // A tile 10240B + B tile 10240B
#define NSTG 3
#define LDS_C 132
#define SMEM_DYN (BM * LDS_C * 4)   // 67584 >= 3*STAGE_BYTES=61440

// -------- device scratch --------
__device__ int    g_cnt[NEXP];
__device__ int    g_tok[NEXP * NTOK];
__device__ float  g_prob[NEXP * NTOK];
__device__ __half g_xh[(size_t)NTOK * HDIM];
__device__ __half g_acth[(size_t)NEXP * NTOK * IDIM];
__device__ __half g_w1h[(size_t)NEXP * I2 * HDIM];
__device__ __half g_w2h[(size_t)NEXP * HDIM * IDIM];

// ---------------- helpers ----------------
__device__ __forceinline__ unsigned int smem_u32(const void* p) {
    return (unsigned int)__cvta_generic_to_shared(p);
}
__device__ __forceinline__ void cp16(unsigned int saddr, const void* g) {
    asm volatile("cp.async.cg.shared.global [%0], [%1], 16;\n" :: "r"(saddr), "l"(g));
}
__device__ __forceinline__ void cp_commit() { asm volatile("cp.async.commit_group;\n"); }
template<int N> __device__ __forceinline__ void cp_wait() {
    asm volatile("cp.async.wait_group %0;\n" :: "n"(N));
}

// =========================================================
__global__ void zero_kernel(float* __restrict__ out) {
    int i = blockIdx.x * blockDim.x + threadIdx.x;
    if (i < NTOK * HDIM) out[i] = 0.0f;
    if (i < NEXP) g_cnt[i] = 0;
}

// =========================================================
// fp32 -> fp16 conversion prepass (exact grids, no bounds check)
// W=0: w1 -> g_w1h, W=1: w2 -> g_w2h, W=2: hidden -> g_xh
// =========================================================
template<int W>
__global__ void cvt_kernel(const float4* __restrict__ src) {
    size_t i = (size_t)blockIdx.x * blockDim.x + threadIdx.x;
    float4 v = src[i];
    half2* dst = (W == 0) ? (half2*)g_w1h : (W == 1) ? (half2*)g_w2h : (half2*)g_xh;
    dst[2 * i]     = __floats2half2_rn(v.x, v.y);
    dst[2 * i + 1] = __floats2half2_rn(v.z, v.w);
}

// =========================================================
__global__ void router_kernel(const float* __restrict__ x,
                              const float* __restrict__ rw,
                              const float* __restrict__ rb) {
    int t = blockIdx.x;
    const float* xr = x + t * HDIM;
    float acc[NEXP];
#pragma unroll
    for (int e = 0; e < NEXP; e++) acc[e] = 0.0f;
    for (int h = threadIdx.x; h < HDIM; h += 128) {
        float xv = xr[h];
#pragma unroll
        for (int e = 0; e < NEXP; e++) acc[e] += xv * rw[e * HDIM + h];
    }
#pragma unroll
    for (int e = 0; e < NEXP; e++) {
#pragma unroll
        for (int o = 16; o > 0; o >>= 1)
            acc[e] += __shfl_down_sync(0xffffffffu, acc[e], o);
    }
    __shared__ float red[4][NEXP];
    int warp = threadIdx.x >> 5, lane = threadIdx.x & 31;
    if (lane == 0) {
#pragma unroll
        for (int e = 0; e < NEXP; e++) red[warp][e] = acc[e];
    }
    __syncthreads();
    if (threadIdx.x == 0) {
        float lg[NEXP];
#pragma unroll
        for (int e = 0; e < NEXP; e++)
            lg[e] = red[0][e] + red[1][e] + red[2][e] + red[3][e] + rb[e];
        int idx[TOPK]; float val[TOPK]; bool used[NEXP];
#pragma unroll
        for (int e = 0; e < NEXP; e++) used[e] = false;
        for (int k = 0; k < TOPK; k++) {
            int bi = -1; float bv = -3.0e38f;
            for (int e = 0; e < NEXP; e++)
                if (!used[e] && lg[e] > bv) { bv = lg[e]; bi = e; }
            used[bi] = true; idx[k] = bi; val[k] = bv;
        }
        float m = val[0], s = 0.0f, p[TOPK];
        for (int k = 0; k < TOPK; k++) { p[k] = expf(val[k] - m); s += p[k]; }
        for (int k = 0; k < TOPK; k++) {
            int e = idx[k];
            int pos = atomicAdd(&g_cnt[e], 1);
            g_tok[e * NTOK + pos]  = t;
            g_prob[e * NTOK + pos] = p[k] / s;
        }
    }
}

// =========================================================
// fp16 grouped GEMM, 128x128 tile, BK=32, 3-stage cp.async ring.
// MODE 0: A = gathered g_xh, B = g_w1h, epilogue glu -> g_acth (half)
// MODE 1: A = g_acth,        B = g_w2h, epilogue bias+prob -> atomic out
// =========================================================
template<int MODE>
__global__ void __launch_bounds__(256, 2)
moe_gemm(const float* __restrict__ bias, float* __restrict__ out) {
    int e   = blockIdx.z;
    int cnt = g_cnt[e];
    int m0  = blockIdx.x * BM;
    if (m0 >= cnt) return;
    int n0  = blockIdx.y * BN;

    const int KDIM  = 2880;                     // HDIM == IDIM
    const int KT    = KDIM / BK;                // 90
    const int BROWS = (MODE == 0) ? I2 : HDIM;

    extern __shared__ char dsm[];
    half* stgA[NSTG];
    half* stgB[NSTG];
#pragma unroll
    for (int s = 0; s < NSTG; s++) {
        stgA[s] = (half*)(dsm + s * STAGE_BYTES);
        stgB[s] = (half*)(dsm + s * STAGE_BYTES + 10240);
    }

    int tid  = threadIdx.x;
    int wid  = tid >> 5, lane = tid & 31;
    int wm   = wid >> 1, wn = wid & 1;

    // ---- copy assignments: 2 x 16B chunks per matrix per thread ----
    const half* ap[2]; const half* bp[2];
    unsigned int off[2];
    {
        const half* bbase = (MODE == 0) ? g_w1h + (size_t)e * I2 * HDIM
                                        : g_w2h + (size_t)e * HDIM * IDIM;
#pragma unroll
        for (int i = 0; i < 2; i++) {
            int id  = tid + i * 256;           // 0..511
            int row = id >> 2, q = id & 3;
            off[i]  = row * 80 + q * 16;       // smem byte offset
            int rb  = n0 + row; if (rb >= BROWS) rb = BROWS - 1;
            bp[i] = bbase + (size_t)rb * KDIM + q * 8;
            int rg = m0 + row;
            int rc = (rg < cnt) ? rg : cnt - 1;
            if (MODE == 0) {
                ap[i] = g_xh + (size_t)g_tok[e * NTOK + rc] * HDIM + q * 8;
            } else {
                ap[i] = g_acth + (size_t)(e * NTOK + rc) * IDIM + q * 8;
            }
        }
    }

    // stage issue: chunk kt -> stage s
    auto issue = [&](int s, int kt) {
        int koff = kt * BK;
        unsigned int a0 = smem_u32(stgA[s]);
        unsigned int b0 = smem_u32(stgB[s]);
#pragma unroll
        for (int i = 0; i < 2; i++) {
            cp16(a0 + off[i], ap[i] + koff);
            cp16(b0 + off[i], bp[i] + koff);
        }
        cp_commit();
    };

    wmma::fragment<wmma::accumulator, 16, 16, 16, float> c[2][4];
#pragma unroll
    for (int i = 0; i < 2; i++)
#pragma unroll
        for (int j = 0; j < 4; j++) wmma::fill_fragment(c[i][j], 0.0f);

    issue(0, 0);
    issue(1, 1);

    for (int kt = 0; kt < KT; kt++) {
        if (kt + 1 < KT) cp_wait<1>(); else cp_wait<0>();
        __syncthreads();
        if (kt + 2 < KT) issue((kt + 2) % NSTG, kt + 2);

        int s = kt % NSTG;
        const half* sa = stgA[s];
        const half* sb = stgB[s];
#pragma unroll
        for (int kk = 0; kk < 2; kk++) {
            wmma::fragment<wmma::matrix_a, 16, 16, 16, half, wmma::row_major> af[2];
#pragma unroll
            for (int i = 0; i < 2; i++)
                wmma::load_matrix_sync(af[i], sa + (wm * 32 + i * 16) * LDSH + kk * 16, LDSH);
#pragma unroll
            for (int j = 0; j < 4; j++) {
                wmma::fragment<wmma::matrix_b, 16, 16, 16, half, wmma::col_major> bf;
                wmma::load_matrix_sync(bf, sb + (wn * 64 + j * 16) * LDSH + kk * 16, LDSH);
#pragma unroll
                for (int i = 0; i < 2; i++)
                    wmma::mma_sync(c[i][j], af[i], bf, c[i][j]);
            }
        }
    }

    __syncthreads();          // all reads of stage smem done; reuse as sC
    float* sC = (float*)dsm;
#pragma unroll
    for (int i = 0; i < 2; i++)
#pragma unroll
        for (int j = 0; j < 4; j++)
            wmma::store_matrix_sync(&sC[(wm * 32 + i * 16) * LDS_C + wn * 64 + j * 16],
                                    c[i][j], LDS_C, wmma::mem_row_major);
    __syncthreads();

    if (MODE == 0) {
        const float* b1e = bias + (size_t)e * I2;
        for (int idx = tid; idx < BM * (BN / 2); idx += 256) {
            int row = idx >> 6;          // 64 pairs per row
            int pr  = idx & 63;
            int rg  = m0 + row;
            if (rg >= cnt) continue;
            float gate = sC[row * LDS_C + 2 * pr]     + b1e[n0 + 2 * pr];
            float up   = sC[row * LDS_C + 2 * pr + 1] + b1e[n0 + 2 * pr + 1];
            gate = fminf(gate, LIMIT_C);
            up   = fminf(fmaxf(up, -LIMIT_C), LIMIT_C);
            float act = (up + 1.0f) * (gate / (1.0f + expf(-ALPHA_C * gate)));
            g_acth[(size_t)(e * NTOK + rg) * IDIM + (n0 >> 1) + pr] = __float2half_rn(act);
        }
    } else {
        for (int idx = tid; idx < BM * BN; idx += 256) {
            int row = idx >> 7;
            int col = idx & 127;
            int rg  = m0 + row;
            int nc  = n0 + col;
            if (rg >= cnt || nc >= HDIM) continue;
            float v = (sC[row * LDS_C + col] + bias[(size_t)e * HDIM + nc]) * g_prob[e * NTOK + rg];
            atomicAdd(&out[(size_t)g_tok[e * NTOK + rg] * HDIM + nc], v);
        }
    }
}

// =========================================================
extern "C" void kernel_launch(void* const* d_in, const int* in_sizes, int n_in,
                              void* d_out, int out_size) {
    const float* hidden = (const float*)d_in[0];
    const float* rw     = (const float*)d_in[1];
    const float* rb     = (const float*)d_in[2];
    const float* w1     = (const float*)d_in[3];
    const float* b1     = (const float*)d_in[4];
    const float* w2     = (const float*)d_in[5];
    const float* b2     = (const float*)d_in[6];
    float* out = (float*)d_out;

    cudaFuncSetAttribute(moe_gemm<0>, cudaFuncAttributeMaxDynamicSharedMemorySize, SMEM_DYN);
    cudaFuncSetAttribute(moe_gemm<1>, cudaFuncAttributeMaxDynamicSharedMemorySize, SMEM_DYN);

    zero_kernel<<<(NTOK * HDIM + 255) / 256, 256>>>(out);
    router_kernel<<<NTOK, 128>>>(hidden, rw, rb);

    // fp32 -> fp16 prepass (exact divisions)
    cvt_kernel<0><<<259200, 256>>>((const float4*)w1);      // 16*5760*2880/4/256
    cvt_kernel<1><<<129600, 256>>>((const float4*)w2);      // 16*2880*2880/4/256
    cvt_kernel<2><<<2880,   256>>>((const float4*)hidden);  // 1024*2880/4/256

    moe_gemm<0><<<dim3(NTOK / BM, I2 / BN, NEXP), 256, SMEM_DYN>>>(b1, nullptr);
    moe_gemm<1><<<dim3(NTOK / BM, (HDIM + BN - 1) / BN, NEXP), 256, SMEM_DYN>>>(b2, out);
}

// round 6
// speedup vs baseline: 3.0598x; 1.2205x over previous
#include <cuda_runtime.h>
#include <cuda_fp16.h>
#include <cstdint>
#include <mma.h>
#include <math.h>

using namespace nvcuda;

#define HDIM 2880
#define NEXP 16
#define I2   5760
#define IDIM 2880
#define NTOK 1024
#define TOPK 4
#define ALPHA_C 1.702f
#define LIMIT_C 7.0f

#define BM 128
#define BN 128
#define BK 32
#define LDSH 40                  // halves per smem row (32 + 8 pad) = 80B
#define ASTG_B 10240             // A stage bytes: 128 rows * 80B
#define BSTG_B 10240             // B stage bytes: 128 rows * 80B
#define LDS_C 132
#define SMEM_DYN (BM * LDS_C * 4)   // 67584 (stages use 3*10240 + 2*10240 = 51200)

// -------- device scratch --------
__device__ int    g_cnt[NEXP];
__device__ int    g_tok[NEXP * NTOK];
__device__ float  g_prob[NEXP * NTOK];
__device__ __half g_xh[(size_t)NTOK * HDIM];
__device__ __half g_acth[(size_t)NEXP * NTOK * IDIM];

// ---------------- helpers ----------------
__device__ __forceinline__ unsigned int smem_u32(const void* p) {
    return (unsigned int)__cvta_generic_to_shared(p);
}
__device__ __forceinline__ void cp16(unsigned int saddr, const void* g) {
    asm volatile("cp.async.cg.shared.global [%0], [%1], 16;\n" :: "r"(saddr), "l"(g));
}
__device__ __forceinline__ void cp_commit() { asm volatile("cp.async.commit_group;\n"); }
template<int N> __device__ __forceinline__ void cp_wait() {
    asm volatile("cp.async.wait_group %0;\n" :: "n"(N));
}

// =========================================================
__global__ void zero_kernel(float* __restrict__ out) {
    int i = blockIdx.x * blockDim.x + threadIdx.x;
    if (i < NTOK * HDIM) out[i] = 0.0f;
    if (i < NEXP) g_cnt[i] = 0;
}

// hidden fp32 -> fp16 (tiny: 5.9 MB)
__global__ void cvt_hidden(const float4* __restrict__ src) {
    size_t i = (size_t)blockIdx.x * blockDim.x + threadIdx.x;
    float4 v = src[i];
    half2* dst = (half2*)g_xh;
    dst[2 * i]     = __floats2half2_rn(v.x, v.y);
    dst[2 * i + 1] = __floats2half2_rn(v.z, v.w);
}

// =========================================================
__global__ void router_kernel(const float* __restrict__ x,
                              const float* __restrict__ rw,
                              const float* __restrict__ rb) {
    int t = blockIdx.x;
    const float* xr = x + t * HDIM;
    float acc[NEXP];
#pragma unroll
    for (int e = 0; e < NEXP; e++) acc[e] = 0.0f;
    for (int h = threadIdx.x; h < HDIM; h += 128) {
        float xv = xr[h];
#pragma unroll
        for (int e = 0; e < NEXP; e++) acc[e] += xv * rw[e * HDIM + h];
    }
#pragma unroll
    for (int e = 0; e < NEXP; e++) {
#pragma unroll
        for (int o = 16; o > 0; o >>= 1)
            acc[e] += __shfl_down_sync(0xffffffffu, acc[e], o);
    }
    __shared__ float red[4][NEXP];
    int warp = threadIdx.x >> 5, lane = threadIdx.x & 31;
    if (lane == 0) {
#pragma unroll
        for (int e = 0; e < NEXP; e++) red[warp][e] = acc[e];
    }
    __syncthreads();
    if (threadIdx.x == 0) {
        float lg[NEXP];
#pragma unroll
        for (int e = 0; e < NEXP; e++)
            lg[e] = red[0][e] + red[1][e] + red[2][e] + red[3][e] + rb[e];
        int idx[TOPK]; float val[TOPK]; bool used[NEXP];
#pragma unroll
        for (int e = 0; e < NEXP; e++) used[e] = false;
        for (int k = 0; k < TOPK; k++) {
            int bi = -1; float bv = -3.0e38f;
            for (int e = 0; e < NEXP; e++)
                if (!used[e] && lg[e] > bv) { bv = lg[e]; bi = e; }
            used[bi] = true; idx[k] = bi; val[k] = bv;
        }
        float m = val[0], s = 0.0f, p[TOPK];
        for (int k = 0; k < TOPK; k++) { p[k] = expf(val[k] - m); s += p[k]; }
        for (int k = 0; k < TOPK; k++) {
            int e = idx[k];
            int pos = atomicAdd(&g_cnt[e], 1);
            g_tok[e * NTOK + pos]  = t;
            g_prob[e * NTOK + pos] = p[k] / s;
        }
    }
}

// =========================================================
// fp16 grouped GEMM, 128x128 tile, BK=32.
// A (fp16 gmem): 3-stage cp.async ring.
// B (fp32 weights): LDG.128 -> regs -> cvt -> STS fp16, 2-stage.
// MODE 0: A = gathered g_xh, B = w1 fp32, epilogue glu -> g_acth
// MODE 1: A = g_acth,        B = w2 fp32, epilogue bias+prob -> atomic out
// =========================================================
template<int MODE>
__global__ void __launch_bounds__(256)
moe_gemm(const float* __restrict__ W,
         const float* __restrict__ bias,
         float* __restrict__ out) {
    int e   = blockIdx.z;
    int cnt = g_cnt[e];
    int m0  = blockIdx.x * BM;
    if (m0 >= cnt) return;
    int n0  = blockIdx.y * BN;

    const int KDIM  = 2880;                     // HDIM == IDIM
    const int KT    = KDIM / BK;                // 90
    const int BROWS = (MODE == 0) ? I2 : HDIM;

    extern __shared__ char dsm[];
    half* stgA[3];
    half* stgB[2];
#pragma unroll
    for (int s = 0; s < 3; s++) stgA[s] = (half*)(dsm + s * ASTG_B);
#pragma unroll
    for (int s = 0; s < 2; s++) stgB[s] = (half*)(dsm + 3 * ASTG_B + s * BSTG_B);

    int tid  = threadIdx.x;
    int wid  = tid >> 5, lane = tid & 31;
    int wm   = wid >> 1, wn = wid & 1;

    // ---- A copy assignment: 2 x 16B chunks per thread ----
    const half* ap[2];
    unsigned int aoff[2];
#pragma unroll
    for (int i = 0; i < 2; i++) {
        int id  = tid + i * 256;           // 0..511
        int row = id >> 2, q = id & 3;     // 128 rows x 4 chunks
        aoff[i] = row * 80 + q * 16;
        int rg = m0 + row;
        int rc = (rg < cnt) ? rg : cnt - 1;
        if (MODE == 0) {
            ap[i] = g_xh + (size_t)g_tok[e * NTOK + rc] * HDIM + q * 8;
        } else {
            ap[i] = g_acth + (size_t)(e * NTOK + rc) * IDIM + q * 8;
        }
    }

    // ---- B load assignment: 4 x float4 chunks per thread ----
    const float* bp[4];
    unsigned int boff[4];
    {
        const float* wbase = W + (size_t)e * BROWS * KDIM;
#pragma unroll
        for (int i = 0; i < 4; i++) {
            int id  = tid + i * 256;       // 0..1023
            int row = id >> 3, q = id & 7; // 128 rows x 8 chunks(4 fp32)
            boff[i] = row * 80 + q * 8;    // fp16 smem bytes
            int rb  = n0 + row; if (rb >= BROWS) rb = BROWS - 1;
            bp[i] = wbase + (size_t)rb * KDIM + q * 4;
        }
    }

    auto ldgB = [&](float4* r, int kt) {
        int koff = kt * BK;
#pragma unroll
        for (int i = 0; i < 4; i++)
            r[i] = *reinterpret_cast<const float4*>(bp[i] + koff);
    };
    auto stsB = [&](const float4* r, int b) {
        unsigned int base = smem_u32(stgB[b]);
#pragma unroll
        for (int i = 0; i < 4; i++) {
            half2 h0 = __floats2half2_rn(r[i].x, r[i].y);
            half2 h1 = __floats2half2_rn(r[i].z, r[i].w);
            unsigned int u0 = *(unsigned int*)&h0;
            unsigned int u1 = *(unsigned int*)&h1;
            asm volatile("st.shared.v2.b32 [%0], {%1, %2};\n"
                         :: "r"(base + boff[i]), "r"(u0), "r"(u1));
        }
    };
    auto issueA = [&](int s, int kt) {
        int koff = kt * BK;
        unsigned int a0 = smem_u32(stgA[s]);
#pragma unroll
        for (int i = 0; i < 2; i++) cp16(a0 + aoff[i], ap[i] + koff);
        cp_commit();
    };

    wmma::fragment<wmma::accumulator, 16, 16, 16, float> c[2][4];
#pragma unroll
    for (int i = 0; i < 2; i++)
#pragma unroll
        for (int j = 0; j < 4; j++) wmma::fill_fragment(c[i][j], 0.0f);

    // ---- prologue ----
    float4 breg[4];
    issueA(0, 0);
    issueA(1, 1);
    ldgB(breg, 0);
    stsB(breg, 0);
    ldgB(breg, 1);              // held for iter 0's STS

    for (int kt = 0; kt < KT; kt++) {
        int s = kt % 3;
        int b = kt & 1;
        if (kt + 1 < KT) cp_wait<1>(); else cp_wait<0>();
        __syncthreads();

        const half* sa = stgA[s];
        const half* sb = stgB[b];
#pragma unroll
        for (int kk = 0; kk < 2; kk++) {
            wmma::fragment<wmma::matrix_a, 16, 16, 16, half, wmma::row_major> af[2];
#pragma unroll
            for (int i = 0; i < 2; i++)
                wmma::load_matrix_sync(af[i], sa + (wm * 32 + i * 16) * LDSH + kk * 16, LDSH);
#pragma unroll
            for (int j = 0; j < 4; j++) {
                wmma::fragment<wmma::matrix_b, 16, 16, 16, half, wmma::col_major> bf;
                wmma::load_matrix_sync(bf, sb + (wn * 64 + j * 16) * LDSH + kk * 16, LDSH);
#pragma unroll
                for (int i = 0; i < 2; i++)
                    wmma::mma_sync(c[i][j], af[i], bf, c[i][j]);
            }
        }

        if (kt + 1 < KT) stsB(breg, b ^ 1);     // breg holds kt+1
        if (kt + 2 < KT) {
            ldgB(breg, kt + 2);
            issueA((kt + 2) % 3, kt + 2);
        }
    }

    __syncthreads();          // stage smem dead; reuse as sC
    float* sC = (float*)dsm;
#pragma unroll
    for (int i = 0; i < 2; i++)
#pragma unroll
        for (int j = 0; j < 4; j++)
            wmma::store_matrix_sync(&sC[(wm * 32 + i * 16) * LDS_C + wn * 64 + j * 16],
                                    c[i][j], LDS_C, wmma::mem_row_major);
    __syncthreads();

    if (MODE == 0) {
        const float* b1e = bias + (size_t)e * I2;
        for (int idx = tid; idx < BM * (BN / 2); idx += 256) {
            int row = idx >> 6;          // 64 pairs per row
            int pr  = idx & 63;
            int rg  = m0 + row;
            if (rg >= cnt) continue;
            float gate = sC[row * LDS_C + 2 * pr]     + b1e[n0 + 2 * pr];
            float up   = sC[row * LDS_C + 2 * pr + 1] + b1e[n0 + 2 * pr + 1];
            gate = fminf(gate, LIMIT_C);
            up   = fminf(fmaxf(up, -LIMIT_C), LIMIT_C);
            float act = (up + 1.0f) * (gate / (1.0f + expf(-ALPHA_C * gate)));
            g_acth[(size_t)(e * NTOK + rg) * IDIM + (n0 >> 1) + pr] = __float2half_rn(act);
        }
    } else {
        for (int idx = tid; idx < BM * BN; idx += 256) {
            int row = idx >> 7;
            int col = idx & 127;
            int rg  = m0 + row;
            int nc  = n0 + col;
            if (rg >= cnt || nc >= HDIM) continue;
            float v = (sC[row * LDS_C + col] + bias[(size_t)e * HDIM + nc]) * g_prob[e * NTOK + rg];
            atomicAdd(&out[(size_t)g_tok[e * NTOK + rg] * HDIM + nc], v);
        }
    }
}

// =========================================================
extern "C" void kernel_launch(void* const* d_in, const int* in_sizes, int n_in,
                              void* d_out, int out_size) {
    const float* hidden = (const float*)d_in[0];
    const float* rw     = (const float*)d_in[1];
    const float* rb     = (const float*)d_in[2];
    const float* w1     = (const float*)d_in[3];
    const float* b1     = (const float*)d_in[4];
    const float* w2     = (const float*)d_in[5];
    const float* b2     = (const float*)d_in[6];
    float* out = (float*)d_out;

    cudaFuncSetAttribute(moe_gemm<0>, cudaFuncAttributeMaxDynamicSharedMemorySize, SMEM_DYN);
    cudaFuncSetAttribute(moe_gemm<1>, cudaFuncAttributeMaxDynamicSharedMemorySize, SMEM_DYN);

    zero_kernel<<<(NTOK * HDIM + 255) / 256, 256>>>(out);
    router_kernel<<<NTOK, 128>>>(hidden, rw, rb);
    cvt_hidden<<<2880, 256>>>((const float4*)hidden);   // 1024*2880/4/256

    moe_gemm<0><<<dim3(NTOK / BM, I2 / BN, NEXP), 256, SMEM_DYN>>>(w1, b1, nullptr);
    moe_gemm<1><<<dim3(NTOK / BM, (HDIM + BN - 1) / BN, NEXP), 256, SMEM_DYN>>>(w2, b2, out);
}